// round 2
// baseline (speedup 1.0000x reference)
#include <cuda_runtime.h>

#define BB 64
#define CC 256
#define HH 56
#define WW 56
#define SH 52
#define SW 52
#define NPLANES (BB*CC)                 // 16384
#define SEEDS_PER_PLANE (SH*SW)         // 2704
#define OUT_PER_PLANE (HH*WW)           // 3136
#define COUNT_M 51380224                // NPLANES * OUT_PER_PLANE
#define TOTAL_F4 (COUNT_M/4)            // 12845056

// Scratch (no allocations allowed): dilated mask as bits, per-plane counts, final scale.
__device__ unsigned long long g_dmask[NPLANES * HH];   // 56 rows/plane, 56 bits/row -> 7.3 MB
__device__ unsigned int       g_pcount[NPLANES];
__device__ float              g_scale;

// ---------------------------------------------------------------------------
// Kernel 1: per-(b,c) plane. Read u (52x52), threshold -> bits, dilate 5x5
// (equivalent to reduce_window max, pad 4/4), write 56 row-bitmasks + count.
// ---------------------------------------------------------------------------
__global__ void __launch_bounds__(64) dilate_kernel(const float* __restrict__ u,
                                                    const float* __restrict__ gammap) {
    __shared__ unsigned char      nib[SH][16];   // 13 nibbles per seed row (padded)
    __shared__ unsigned long long rowd[SH];      // row-dilated seed rows
    __shared__ unsigned int       wsum[2];

    const int plane = blockIdx.x;
    const int tid   = threadIdx.x;
    const float gamma = *gammap;

    // Coalesced float4 load of the whole 52x52 plane; 52 % 4 == 0 so each
    // float4 stays inside one seed row. 676 float4s / 64 threads.
    const float4* up = (const float4*)u + (size_t)plane * (SEEDS_PER_PLANE / 4);
    for (int f = tid; f < SEEDS_PER_PLANE / 4; f += 64) {
        float4 v = up[f];
        int row = f / 13;
        int cg  = f - row * 13;
        unsigned n = (v.x < gamma ? 1u : 0u) | (v.y < gamma ? 2u : 0u)
                   | (v.z < gamma ? 4u : 0u) | (v.w < gamma ? 8u : 0u);
        nib[row][cg] = (unsigned char)n;
    }
    __syncthreads();

    // Horizontal dilation: out bit j = OR of seed bits [j-4, j]
    //   => r | r<<1 | r<<2 | r<<3 | r<<4   (bits 0..55)
    if (tid < SH) {
        unsigned long long r = 0;
        #pragma unroll
        for (int c = 0; c < 13; c++)
            r |= ((unsigned long long)nib[tid][c]) << (4 * c);
        unsigned long long t = r | (r << 1);
        t |= (t << 2);              // r|r<<1|r<<2|r<<3
        r  = t | (r << 4);
        rowd[tid] = r;
    }
    __syncthreads();

    // Vertical dilation: out row i = OR of row-dilated rows [max(0,i-4), min(51,i)]
    unsigned cnt = 0;
    if (tid < HH) {
        int lo = tid - 4; if (lo < 0) lo = 0;
        int hi = tid;     if (hi > SH - 1) hi = SH - 1;
        unsigned long long d = 0;
        for (int p = lo; p <= hi; p++) d |= rowd[p];
        g_dmask[(size_t)plane * HH + tid] = d;
        cnt = __popcll(d);
    }

    // Block reduction of dropped-element count (deterministic, no atomics).
    #pragma unroll
    for (int o = 16; o; o >>= 1) cnt += __shfl_down_sync(0xffffffffu, cnt, o);
    if ((tid & 31) == 0) wsum[tid >> 5] = cnt;
    __syncthreads();
    if (tid == 0) g_pcount[plane] = wsum[0] + wsum[1];
}

// ---------------------------------------------------------------------------
// Kernel 2: reduce 16384 plane counts, compute normalization scale once.
// ---------------------------------------------------------------------------
__global__ void __launch_bounds__(256) scale_kernel() {
    __shared__ unsigned int s[256];
    unsigned int tot = 0;
    for (int i = threadIdx.x; i < NPLANES; i += 256) tot += g_pcount[i];
    s[threadIdx.x] = tot;
    __syncthreads();
    for (int o = 128; o; o >>= 1) {
        if (threadIdx.x < o) s[threadIdx.x] += s[threadIdx.x + o];
        __syncthreads();
    }
    if (threadIdx.x == 0) {
        double ones = (double)COUNT_M - (double)s[0];   // kept elements
        g_scale = (float)((double)COUNT_M / (ones + 1e-12));
    }
}

// ---------------------------------------------------------------------------
// Kernel 3: apply. One float4 per thread; 4 mask bits from one (broadcast)
// uint64 row word. out = bit ? 0 : x * scale.
// ---------------------------------------------------------------------------
__global__ void __launch_bounds__(256) apply_kernel(const float* __restrict__ x,
                                                    float* __restrict__ out) {
    const float s = g_scale;
    unsigned f = blockIdx.x * 256u + threadIdx.x;      // float4 index < 12845056

    unsigned plane = f / 784u;                         // 784 = 3136/4 f4 per plane
    unsigned rem   = f - plane * 784u;
    unsigned row   = rem / 14u;                        // 14 f4 per 56-wide row
    unsigned cg    = rem - row * 14u;

    unsigned long long d = g_dmask[(size_t)plane * HH + row];
    unsigned bits = (unsigned)(d >> (4u * cg)) & 0xFu;

    float4 v = ((const float4*)x)[f];
    float4 o;
    o.x = (bits & 1u) ? 0.0f : v.x * s;
    o.y = (bits & 2u) ? 0.0f : v.y * s;
    o.z = (bits & 4u) ? 0.0f : v.z * s;
    o.w = (bits & 8u) ? 0.0f : v.w * s;
    ((float4*)out)[f] = o;
}

// ---------------------------------------------------------------------------
extern "C" void kernel_launch(void* const* d_in, const int* in_sizes, int n_in,
                              void* d_out, int out_size) {
    // Identify inputs by element count (robust to metadata ordering).
    const float* x = nullptr;
    const float* u = nullptr;
    const float* g = nullptr;
    for (int i = 0; i < n_in; i++) {
        if (in_sizes[i] == COUNT_M)                x = (const float*)d_in[i];
        else if (in_sizes[i] == NPLANES * SEEDS_PER_PLANE) u = (const float*)d_in[i];
        else if (in_sizes[i] == 1)                 g = (const float*)d_in[i];
    }
    float* out = (float*)d_out;

    dilate_kernel<<<NPLANES, 64>>>(u, g);
    scale_kernel<<<1, 256>>>();
    apply_kernel<<<TOTAL_F4 / 256, 256>>>(x, out);
}